// round 1
// baseline (speedup 1.0000x reference)
#include <cuda_runtime.h>
#include <cstdint>

#define S_LEN 2048
#define D_HEAD 128
#define N_BH 32          // B*H = 2*16
#define BM 128
#define BN 64
#define THREADS 256      // 8 warps, each owns 16 rows of the Q tile
#define QSTR 132         // padded smem row stride (mod 32 == 4 -> conflict-free frags)
#define KSTR 132
#define PSTR 68          // 64 + 4, same property
#define LOG2E 1.4426950408889634f

#define QS_OFF 0
#define KS_OFF (QS_OFF + BM * QSTR)
#define VS_OFF (KS_OFF + BN * KSTR)
#define PS_OFF (VS_OFF + BN * KSTR)
#define SMEM_FLOATS (PS_OFF + BM * PSTR)   // 42496 floats = 169984 B

static __device__ __forceinline__ uint32_t f2tf(float x) {
  uint32_t r; asm("cvt.rna.tf32.f32 %0, %1;" : "=r"(r) : "f"(x)); return r;
}
static __device__ __forceinline__ float ex2f(float x) {
  float y; asm("ex2.approx.ftz.f32 %0, %1;" : "=f"(y) : "f"(x)); return y;
}
static __device__ __forceinline__ void mma8(float d[4], const uint32_t a[4],
                                            uint32_t b0, uint32_t b1) {
  asm volatile(
    "mma.sync.aligned.m16n8k8.row.col.f32.tf32.tf32.f32 "
    "{%0,%1,%2,%3}, {%4,%5,%6,%7}, {%8,%9}, {%0,%1,%2,%3};"
    : "+f"(d[0]), "+f"(d[1]), "+f"(d[2]), "+f"(d[3])
    : "r"(a[0]), "r"(a[1]), "r"(a[2]), "r"(a[3]), "r"(b0), "r"(b1));
}

extern __shared__ float smf[];

__global__ void __launch_bounds__(THREADS, 1)
fattn_tf32(const float* __restrict__ Qg, const float* __restrict__ Kg,
           const float* __restrict__ Vg, float* __restrict__ Og)
{
  const int tid = threadIdx.x;
  const int bh  = blockIdx.y;
  const int q0  = blockIdx.x * BM;
  const size_t base = (size_t)bh * S_LEN * D_HEAD;

  const float* Qb = Qg + base + (size_t)q0 * D_HEAD;
  const float* Kb = Kg + base;
  const float* Vb = Vg + base;

  float* QS = smf + QS_OFF;
  float* KS = smf + KS_OFF;
  float* VS = smf + VS_OFF;
  float* PS = smf + PS_OFF;

  // ---- load Q tile (BM x 128) into padded smem ----
  #pragma unroll
  for (int i = 0; i < (BM * D_HEAD / 4) / THREADS; ++i) {   // 16 iters
    int idx = i * THREADS + tid;
    int row = idx >> 5;          // 32 float4 per row
    int c4  = idx & 31;
    float4 v = *reinterpret_cast<const float4*>(Qb + row * D_HEAD + c4 * 4);
    *reinterpret_cast<float4*>(QS + row * QSTR + c4 * 4) = v;
  }

  const int lane = tid & 31;
  const int wid  = tid >> 5;
  const int gid  = lane >> 2;   // 0..7
  const int tg   = lane & 3;    // 0..3
  const int row0 = wid * 16;

  // O accumulators: 16 n-tiles of 16x8 over D=128
  float o[16][4];
  #pragma unroll
  for (int n = 0; n < 16; ++n) { o[n][0] = o[n][1] = o[n][2] = o[n][3] = 0.f; }
  float mA = -INFINITY, mB = -INFINITY;  // rows row0+gid and row0+gid+8
  float lA = 0.f, lB = 0.f;

  for (int t = 0; t < S_LEN / BN; ++t) {
    __syncthreads();   // previous iteration done reading K/V
    const float* Kt = Kb + (size_t)t * BN * D_HEAD;
    const float* Vt = Vb + (size_t)t * BN * D_HEAD;
    #pragma unroll
    for (int i = 0; i < (BN * D_HEAD / 4) / THREADS; ++i) { // 8 iters
      int idx = i * THREADS + tid;
      int row = idx >> 5;
      int c4  = idx & 31;
      *reinterpret_cast<float4*>(KS + row * KSTR + c4 * 4) =
          *reinterpret_cast<const float4*>(Kt + row * D_HEAD + c4 * 4);
      *reinterpret_cast<float4*>(VS + row * KSTR + c4 * 4) =
          *reinterpret_cast<const float4*>(Vt + row * D_HEAD + c4 * 4);
    }
    __syncthreads();

    // ---- S = Q @ K^T  (3xTF32: qh*kh + qh*kl + ql*kh) ----
    float s[8][4];
    #pragma unroll
    for (int n = 0; n < 8; ++n) { s[n][0] = s[n][1] = s[n][2] = s[n][3] = 0.f; }

    #pragma unroll 4
    for (int k = 0; k < 16; ++k) {
      const int kc = k * 8;
      float qa0 = QS[(row0 + gid)     * QSTR + kc + tg];
      float qa1 = QS[(row0 + gid + 8) * QSTR + kc + tg];
      float qa2 = QS[(row0 + gid)     * QSTR + kc + tg + 4];
      float qa3 = QS[(row0 + gid + 8) * QSTR + kc + tg + 4];
      uint32_t ah[4] = { f2tf(qa0), f2tf(qa1), f2tf(qa2), f2tf(qa3) };
      uint32_t al[4] = { f2tf(qa0 - __uint_as_float(ah[0])),
                         f2tf(qa1 - __uint_as_float(ah[1])),
                         f2tf(qa2 - __uint_as_float(ah[2])),
                         f2tf(qa3 - __uint_as_float(ah[3])) };
      #pragma unroll
      for (int n = 0; n < 8; ++n) {
        float kb0 = KS[(n * 8 + gid) * KSTR + kc + tg];
        float kb1 = KS[(n * 8 + gid) * KSTR + kc + tg + 4];
        uint32_t bh0 = f2tf(kb0), bh1 = f2tf(kb1);
        uint32_t bl0 = f2tf(kb0 - __uint_as_float(bh0));
        uint32_t bl1 = f2tf(kb1 - __uint_as_float(bh1));
        mma8(s[n], ah, bh0, bh1);
        mma8(s[n], ah, bl0, bl1);
        mma8(s[n], al, bh0, bh1);
      }
    }

    // ---- online softmax (per-lane rows: row0+gid, row0+gid+8) ----
    float mx0 = s[0][0], mx1 = s[0][2];
    #pragma unroll
    for (int n = 0; n < 8; ++n) {
      mx0 = fmaxf(mx0, fmaxf(s[n][0], s[n][1]));
      mx1 = fmaxf(mx1, fmaxf(s[n][2], s[n][3]));
    }
    mx0 = fmaxf(mx0, __shfl_xor_sync(0xffffffffu, mx0, 1));
    mx0 = fmaxf(mx0, __shfl_xor_sync(0xffffffffu, mx0, 2));
    mx1 = fmaxf(mx1, __shfl_xor_sync(0xffffffffu, mx1, 1));
    mx1 = fmaxf(mx1, __shfl_xor_sync(0xffffffffu, mx1, 2));

    float mnA = fmaxf(mA, mx0);
    float mnB = fmaxf(mB, mx1);
    float aAc = ex2f((mA - mnA) * LOG2E);
    float aBc = ex2f((mB - mnB) * LOG2E);

    float psA = 0.f, psB = 0.f;
    #pragma unroll
    for (int n = 0; n < 8; ++n) {
      float p0 = __uint_as_float(f2tf(ex2f((s[n][0] - mnA) * LOG2E)));
      float p1 = __uint_as_float(f2tf(ex2f((s[n][1] - mnA) * LOG2E)));
      float p2 = __uint_as_float(f2tf(ex2f((s[n][2] - mnB) * LOG2E)));
      float p3 = __uint_as_float(f2tf(ex2f((s[n][3] - mnB) * LOG2E)));
      s[n][0] = p0; s[n][1] = p1; s[n][2] = p2; s[n][3] = p3;
      psA += p0 + p1;
      psB += p2 + p3;
    }
    psA += __shfl_xor_sync(0xffffffffu, psA, 1);
    psA += __shfl_xor_sync(0xffffffffu, psA, 2);
    psB += __shfl_xor_sync(0xffffffffu, psB, 1);
    psB += __shfl_xor_sync(0xffffffffu, psB, 2);

    lA = lA * aAc + psA;
    lB = lB * aBc + psB;
    mA = mnA; mB = mnB;

    #pragma unroll
    for (int n = 0; n < 16; ++n) {
      o[n][0] *= aAc; o[n][1] *= aAc;
      o[n][2] *= aBc; o[n][3] *= aBc;
    }

    // ---- stage P (already tf32-rounded) for the PV mma ----
    #pragma unroll
    for (int n = 0; n < 8; ++n) {
      *reinterpret_cast<float2*>(PS + (row0 + gid)     * PSTR + n * 8 + 2 * tg) =
          make_float2(s[n][0], s[n][1]);
      *reinterpret_cast<float2*>(PS + (row0 + gid + 8) * PSTR + n * 8 + 2 * tg) =
          make_float2(s[n][2], s[n][3]);
    }
    __syncwarp();

    // ---- O += P @ V  (2xTF32: P*vh + P*vl) ----
    #pragma unroll 2
    for (int k = 0; k < 8; ++k) {
      const int kc = k * 8;
      uint32_t a[4] = {
        __float_as_uint(PS[(row0 + gid)     * PSTR + kc + tg]),
        __float_as_uint(PS[(row0 + gid + 8) * PSTR + kc + tg]),
        __float_as_uint(PS[(row0 + gid)     * PSTR + kc + tg + 4]),
        __float_as_uint(PS[(row0 + gid + 8) * PSTR + kc + tg + 4]) };
      #pragma unroll
      for (int n = 0; n < 16; ++n) {
        float vb0 = VS[(kc + tg)     * KSTR + n * 8 + gid];
        float vb1 = VS[(kc + tg + 4) * KSTR + n * 8 + gid];
        uint32_t bh0 = f2tf(vb0), bh1 = f2tf(vb1);
        uint32_t bl0 = f2tf(vb0 - __uint_as_float(bh0));
        uint32_t bl1 = f2tf(vb1 - __uint_as_float(bh1));
        mma8(o[n], a, bh0, bh1);
        mma8(o[n], a, bl0, bl1);
      }
    }
  }

  // ---- epilogue: O / l ----
  const float ilA = 1.f / lA;
  const float ilB = 1.f / lB;
  float* Ob = Og + base + (size_t)q0 * D_HEAD;
  #pragma unroll
  for (int n = 0; n < 16; ++n) {
    int col = n * 8 + 2 * tg;
    *reinterpret_cast<float2*>(Ob + (size_t)(row0 + gid) * D_HEAD + col) =
        make_float2(o[n][0] * ilA, o[n][1] * ilA);
    *reinterpret_cast<float2*>(Ob + (size_t)(row0 + gid + 8) * D_HEAD + col) =
        make_float2(o[n][2] * ilB, o[n][3] * ilB);
  }
}

extern "C" void kernel_launch(void* const* d_in, const int* in_sizes, int n_in,
                              void* d_out, int out_size) {
  const float* Q = (const float*)d_in[0];   // input
  const float* K = (const float*)d_in[1];   // weight
  const float* V = (const float*)d_in[2];   // value
  float* O = (float*)d_out;

  cudaFuncSetAttribute(fattn_tf32, cudaFuncAttributeMaxDynamicSharedMemorySize,
                       SMEM_FLOATS * sizeof(float));
  dim3 grid(S_LEN / BM, N_BH);
  fattn_tf32<<<grid, THREADS, SMEM_FLOATS * sizeof(float)>>>(Q, K, V, O);
}

// round 3
// speedup vs baseline: 2.1581x; 2.1581x over previous
#include <cuda_runtime.h>
#include <cuda_bf16.h>
#include <cstdint>

#define S_LEN 2048
#define D_HEAD 128
#define N_BH 32          // B*H
#define BM 128
#define BN 64
#define THREADS 256      // 8 warps, each owns 16 Q rows
#define STR 136          // bf16 elems per smem row (272B, conflict-free ldsm)
#define LOG2E 1.4426950408889634f

#define QH_OFF 0
#define QL_OFF (QH_OFF + BM * STR)
#define KH_OFF (QL_OFF + BM * STR)
#define KL_OFF (KH_OFF + BN * STR)
#define VH_OFF (KL_OFF + BN * STR)
#define VL_OFF (VH_OFF + BN * STR)
#define SMEM_ELEMS (VL_OFF + BN * STR)   // 69632 bf16 = 139264 B

static __device__ __forceinline__ float ex2f(float x) {
  float y; asm("ex2.approx.ftz.f32 %0, %1;" : "=f"(y) : "f"(x)); return y;
}
static __device__ __forceinline__ void mma16(float d[4], const uint32_t a[4],
                                             uint32_t b0, uint32_t b1) {
  asm("mma.sync.aligned.m16n8k16.row.col.f32.bf16.bf16.f32 "
      "{%0,%1,%2,%3}, {%4,%5,%6,%7}, {%8,%9}, {%0,%1,%2,%3};"
      : "+f"(d[0]), "+f"(d[1]), "+f"(d[2]), "+f"(d[3])
      : "r"(a[0]), "r"(a[1]), "r"(a[2]), "r"(a[3]), "r"(b0), "r"(b1));
}
static __device__ __forceinline__ void ldsm4(uint32_t r[4], uint32_t addr) {
  asm volatile("ldmatrix.sync.aligned.m8n8.x4.shared.b16 {%0,%1,%2,%3}, [%4];"
               : "=r"(r[0]), "=r"(r[1]), "=r"(r[2]), "=r"(r[3]) : "r"(addr));
}
static __device__ __forceinline__ void ldsm4t(uint32_t r[4], uint32_t addr) {
  asm volatile("ldmatrix.sync.aligned.m8n8.x4.trans.shared.b16 {%0,%1,%2,%3}, [%4];"
               : "=r"(r[0]), "=r"(r[1]), "=r"(r[2]), "=r"(r[3]) : "r"(addr));
}
// split (x0,x1) into packed bf16 hi pair and bf16 lo (residual) pair
static __device__ __forceinline__ void split2(float x0, float x1,
                                              uint32_t& h, uint32_t& l) {
  __nv_bfloat16 h0 = __float2bfloat16_rn(x0);
  __nv_bfloat16 h1 = __float2bfloat16_rn(x1);
  __nv_bfloat162 hp = __halves2bfloat162(h0, h1);
  h = *reinterpret_cast<uint32_t*>(&hp);
  __nv_bfloat162 lp = __floats2bfloat162_rn(x0 - __bfloat162float(h0),
                                            x1 - __bfloat162float(h1));
  l = *reinterpret_cast<uint32_t*>(&lp);
}

extern __shared__ __align__(16) __nv_bfloat16 smb[];

__global__ void __launch_bounds__(THREADS, 1)
fattn_bf16x2(const float* __restrict__ Qg, const float* __restrict__ Kg,
             const float* __restrict__ Vg, float* __restrict__ Og)
{
  const int tid = threadIdx.x;
  const int bh  = blockIdx.y;
  const int q0  = blockIdx.x * BM;
  const size_t base = (size_t)bh * S_LEN * D_HEAD;

  const float* Qb = Qg + base + (size_t)q0 * D_HEAD;
  const float* Kb = Kg + base;
  const float* Vb = Vg + base;

  const int lane = tid & 31;
  const int wid  = tid >> 5;
  const int row0 = wid * 16;

  // ---- load + split Q tile (BM x 128) into bf16 hi/lo planes ----
  #pragma unroll
  for (int i = 0; i < 16; ++i) {
    int idx = i * THREADS + tid;
    int row = idx >> 5;
    int c4  = idx & 31;
    float4 v = *reinterpret_cast<const float4*>(Qb + row * D_HEAD + 4 * c4);
    uint32_t h01, l01, h23, l23;
    split2(v.x, v.y, h01, l01);
    split2(v.z, v.w, h23, l23);
    *reinterpret_cast<uint2*>(smb + QH_OFF + row * STR + 4 * c4) = make_uint2(h01, h23);
    *reinterpret_cast<uint2*>(smb + QL_OFF + row * STR + 4 * c4) = make_uint2(l01, l23);
  }

  const uint32_t smu = (uint32_t)__cvta_generic_to_shared(smb);
  // ldmatrix per-lane base addresses (byte offsets; elem*2)
  const uint32_t qbase = smu + 2u * ((row0 + (lane & 15)) * STR + (lane >> 4) * 8);
  const uint32_t kbase = smu + 2u * (((lane & 7) + ((lane >> 4) << 3)) * STR
                                     + (((lane >> 3) & 1) << 3));
  const uint32_t vbase = smu + 2u * (((lane & 7) + (((lane >> 3) & 1) << 3)) * STR
                                     + ((lane >> 4) << 3));

  float o[16][4];
  #pragma unroll
  for (int n = 0; n < 16; ++n) { o[n][0] = o[n][1] = o[n][2] = o[n][3] = 0.f; }
  float mA = -INFINITY, mB = -INFINITY;
  float lA = 0.f, lB = 0.f;

  for (int t = 0; t < S_LEN / BN; ++t) {
    __syncthreads();
    const float* Kt = Kb + (size_t)t * BN * D_HEAD;
    const float* Vt = Vb + (size_t)t * BN * D_HEAD;
    #pragma unroll
    for (int i = 0; i < 8; ++i) {
      int idx = i * THREADS + tid;
      int row = idx >> 5;
      int c4  = idx & 31;
      float4 kv = *reinterpret_cast<const float4*>(Kt + row * D_HEAD + 4 * c4);
      uint32_t h01, l01, h23, l23;
      split2(kv.x, kv.y, h01, l01);
      split2(kv.z, kv.w, h23, l23);
      *reinterpret_cast<uint2*>(smb + KH_OFF + row * STR + 4 * c4) = make_uint2(h01, h23);
      *reinterpret_cast<uint2*>(smb + KL_OFF + row * STR + 4 * c4) = make_uint2(l01, l23);
      float4 vv = *reinterpret_cast<const float4*>(Vt + row * D_HEAD + 4 * c4);
      split2(vv.x, vv.y, h01, l01);
      split2(vv.z, vv.w, h23, l23);
      *reinterpret_cast<uint2*>(smb + VH_OFF + row * STR + 4 * c4) = make_uint2(h01, h23);
      *reinterpret_cast<uint2*>(smb + VL_OFF + row * STR + 4 * c4) = make_uint2(l01, l23);
    }
    __syncthreads();

    // ---- S = Q K^T : 3-term split-bf16 (qh*kh + qh*kl + ql*kh) ----
    float s[8][4];
    #pragma unroll
    for (int n = 0; n < 8; ++n) { s[n][0] = s[n][1] = s[n][2] = s[n][3] = 0.f; }

    #pragma unroll
    for (int c = 0; c < 8; ++c) {
      const int kc = c * 16;
      uint32_t qh[4], ql[4];
      ldsm4(qh, qbase + 2u * (QH_OFF + kc));
      ldsm4(ql, qbase + 2u * (QL_OFF + kc));
      #pragma unroll
      for (int n2 = 0; n2 < 4; ++n2) {
        uint32_t kh[4], kl[4];
        ldsm4(kh, kbase + 2u * (KH_OFF + n2 * 16 * STR + kc));
        ldsm4(kl, kbase + 2u * (KL_OFF + n2 * 16 * STR + kc));
        mma16(s[2 * n2],     qh, kh[0], kh[1]);
        mma16(s[2 * n2 + 1], qh, kh[2], kh[3]);
        mma16(s[2 * n2],     qh, kl[0], kl[1]);
        mma16(s[2 * n2 + 1], qh, kl[2], kl[3]);
        mma16(s[2 * n2],     ql, kh[0], kh[1]);
        mma16(s[2 * n2 + 1], ql, kh[2], kh[3]);
      }
    }

    // ---- online softmax (rows row0+gid, row0+gid+8) ----
    float mx0 = s[0][0], mx1 = s[0][2];
    #pragma unroll
    for (int n = 0; n < 8; ++n) {
      mx0 = fmaxf(mx0, fmaxf(s[n][0], s[n][1]));
      mx1 = fmaxf(mx1, fmaxf(s[n][2], s[n][3]));
    }
    mx0 = fmaxf(mx0, __shfl_xor_sync(0xffffffffu, mx0, 1));
    mx0 = fmaxf(mx0, __shfl_xor_sync(0xffffffffu, mx0, 2));
    mx1 = fmaxf(mx1, __shfl_xor_sync(0xffffffffu, mx1, 1));
    mx1 = fmaxf(mx1, __shfl_xor_sync(0xffffffffu, mx1, 2));

    float mnA = fmaxf(mA, mx0);
    float mnB = fmaxf(mB, mx1);
    float aAc = ex2f((mA - mnA) * LOG2E);
    float aBc = ex2f((mB - mnB) * LOG2E);

    float psA = 0.f, psB = 0.f;
    #pragma unroll
    for (int n = 0; n < 8; ++n) {
      float p0 = ex2f((s[n][0] - mnA) * LOG2E);
      float p1 = ex2f((s[n][1] - mnA) * LOG2E);
      float p2 = ex2f((s[n][2] - mnB) * LOG2E);
      float p3 = ex2f((s[n][3] - mnB) * LOG2E);
      s[n][0] = p0; s[n][1] = p1; s[n][2] = p2; s[n][3] = p3;
      psA += p0 + p1;
      psB += p2 + p3;
    }
    psA += __shfl_xor_sync(0xffffffffu, psA, 1);
    psA += __shfl_xor_sync(0xffffffffu, psA, 2);
    psB += __shfl_xor_sync(0xffffffffu, psB, 1);
    psB += __shfl_xor_sync(0xffffffffu, psB, 2);

    lA = lA * aAc + psA;
    lB = lB * aBc + psB;
    mA = mnA; mB = mnB;

    #pragma unroll
    for (int n = 0; n < 16; ++n) {
      o[n][0] *= aAc; o[n][1] *= aAc;
      o[n][2] *= aBc; o[n][3] *= aBc;
    }

    // ---- O += P V : 3-term split-bf16 (Ph*Vh + Pl*Vh + Ph*Vl) ----
    // P A-fragments come straight from the S accumulator registers.
    #pragma unroll
    for (int c = 0; c < 4; ++c) {
      const int kc = c * 16;
      uint32_t aPh[4], aPl[4];
      split2(s[2 * c][0],     s[2 * c][1],     aPh[0], aPl[0]);
      split2(s[2 * c][2],     s[2 * c][3],     aPh[1], aPl[1]);
      split2(s[2 * c + 1][0], s[2 * c + 1][1], aPh[2], aPl[2]);
      split2(s[2 * c + 1][2], s[2 * c + 1][3], aPh[3], aPl[3]);
      #pragma unroll
      for (int n2 = 0; n2 < 8; ++n2) {
        const int d0 = n2 * 16;
        uint32_t vh[4], vl[4];
        ldsm4t(vh, vbase + 2u * (VH_OFF + kc * STR + d0));
        ldsm4t(vl, vbase + 2u * (VL_OFF + kc * STR + d0));
        mma16(o[2 * n2],     aPh, vh[0], vh[1]);
        mma16(o[2 * n2 + 1], aPh, vh[2], vh[3]);
        mma16(o[2 * n2],     aPl, vh[0], vh[1]);
        mma16(o[2 * n2 + 1], aPl, vh[2], vh[3]);
        mma16(o[2 * n2],     aPh, vl[0], vl[1]);
        mma16(o[2 * n2 + 1], aPh, vl[2], vl[3]);
      }
    }
  }

  // ---- epilogue: O / l ----
  const int gid = lane >> 2;
  const int tg  = lane & 3;
  const float ilA = 1.f / lA;
  const float ilB = 1.f / lB;
  float* Ob = Og + base + (size_t)q0 * D_HEAD;
  #pragma unroll
  for (int n = 0; n < 16; ++n) {
    int col = n * 8 + 2 * tg;
    *reinterpret_cast<float2*>(Ob + (size_t)(row0 + gid) * D_HEAD + col) =
        make_float2(o[n][0] * ilA, o[n][1] * ilA);
    *reinterpret_cast<float2*>(Ob + (size_t)(row0 + gid + 8) * D_HEAD + col) =
        make_float2(o[n][2] * ilB, o[n][3] * ilB);
  }
}

extern "C" void kernel_launch(void* const* d_in, const int* in_sizes, int n_in,
                              void* d_out, int out_size) {
  const float* Q = (const float*)d_in[0];
  const float* K = (const float*)d_in[1];
  const float* V = (const float*)d_in[2];
  float* O = (float*)d_out;

  cudaFuncSetAttribute(fattn_bf16x2, cudaFuncAttributeMaxDynamicSharedMemorySize,
                       SMEM_ELEMS * sizeof(__nv_bfloat16));
  dim3 grid(S_LEN / BM, N_BH);
  fattn_bf16x2<<<grid, THREADS, SMEM_ELEMS * sizeof(__nv_bfloat16)>>>(Q, K, V, O);
}

// round 5
// speedup vs baseline: 2.9289x; 1.3572x over previous
#include <cuda_runtime.h>
#include <cuda_bf16.h>
#include <cuda_fp16.h>
#include <cstdint>

#define S_LEN 2048
#define D_HEAD 128
#define N_BH 32
#define BM 128
#define BN 64
#define NT (S_LEN / BN)
#define THREADS 256
#define STR 136              // padded row stride in 16-bit elems
#define LOG2E 1.4426950408889634f

// ---- smem layout (byte offsets, all 16B aligned) ----
#define QH_B 0               // 128*136*2 = 34816
#define QL_B 34816
#define KH_B 69632           // 64*136*2 = 17408
#define KL_B 87040
#define VF_B 104448          // fp16 V plane, 17408
#define RAWK_B 121856        // 64*128*4 = 32768
#define RAWV_B 154624
#define SMEM_BYTES 187392

// element (16-bit) offsets for ldsm address math
#define QH_E 0
#define QL_E 17408
#define KH_E 34816
#define KL_E 43520
#define VF_E 52224

static __device__ __forceinline__ float ex2f(float x) {
  float y; asm("ex2.approx.ftz.f32 %0, %1;" : "=f"(y) : "f"(x)); return y;
}
static __device__ __forceinline__ void mma16b(float d[4], const uint32_t a[4],
                                              uint32_t b0, uint32_t b1) {
  asm("mma.sync.aligned.m16n8k16.row.col.f32.bf16.bf16.f32 "
      "{%0,%1,%2,%3}, {%4,%5,%6,%7}, {%8,%9}, {%0,%1,%2,%3};"
      : "+f"(d[0]), "+f"(d[1]), "+f"(d[2]), "+f"(d[3])
      : "r"(a[0]), "r"(a[1]), "r"(a[2]), "r"(a[3]), "r"(b0), "r"(b1));
}
static __device__ __forceinline__ void mma16h(float d[4], const uint32_t a[4],
                                              uint32_t b0, uint32_t b1) {
  asm("mma.sync.aligned.m16n8k16.row.col.f32.f16.f16.f32 "
      "{%0,%1,%2,%3}, {%4,%5,%6,%7}, {%8,%9}, {%0,%1,%2,%3};"
      : "+f"(d[0]), "+f"(d[1]), "+f"(d[2]), "+f"(d[3])
      : "r"(a[0]), "r"(a[1]), "r"(a[2]), "r"(a[3]), "r"(b0), "r"(b1));
}
static __device__ __forceinline__ void ldsm4(uint32_t r[4], uint32_t addr) {
  asm volatile("ldmatrix.sync.aligned.m8n8.x4.shared.b16 {%0,%1,%2,%3}, [%4];"
               : "=r"(r[0]), "=r"(r[1]), "=r"(r[2]), "=r"(r[3]) : "r"(addr));
}
static __device__ __forceinline__ void ldsm4t(uint32_t r[4], uint32_t addr) {
  asm volatile("ldmatrix.sync.aligned.m8n8.x4.trans.shared.b16 {%0,%1,%2,%3}, [%4];"
               : "=r"(r[0]), "=r"(r[1]), "=r"(r[2]), "=r"(r[3]) : "r"(addr));
}
static __device__ __forceinline__ void split2(float x0, float x1,
                                              uint32_t& h, uint32_t& l) {
  __nv_bfloat16 h0 = __float2bfloat16_rn(x0);
  __nv_bfloat16 h1 = __float2bfloat16_rn(x1);
  __nv_bfloat162 hp = __halves2bfloat162(h0, h1);
  h = *reinterpret_cast<uint32_t*>(&hp);
  __nv_bfloat162 lp = __floats2bfloat162_rn(x0 - __bfloat162float(h0),
                                            x1 - __bfloat162float(h1));
  l = *reinterpret_cast<uint32_t*>(&lp);
}
#define CPA16(dst, src) \
  asm volatile("cp.async.cg.shared.global [%0], [%1], 16;" :: "r"(dst), "l"(src))
#define CPA_COMMIT() asm volatile("cp.async.commit_group;" ::: "memory")
#define CPA_WAIT0() asm volatile("cp.async.wait_group 0;" ::: "memory")

extern __shared__ __align__(16) char smb[];

__global__ void __launch_bounds__(THREADS, 1)
fattn_h(const float* __restrict__ Qg, const float* __restrict__ Kg,
        const float* __restrict__ Vg, float* __restrict__ Og)
{
  const int tid = threadIdx.x;
  const int bh  = blockIdx.y;
  const int q0  = blockIdx.x * BM;
  const size_t base = (size_t)bh * S_LEN * D_HEAD;

  const float* Qb = Qg + base + (size_t)q0 * D_HEAD;
  const float* Kb = Kg + base;
  const float* Vb = Vg + base;

  const int lane = tid & 31;
  const int wid  = tid >> 5;
  const int row0 = wid * 16;
  const uint32_t smu = (uint32_t)__cvta_generic_to_shared(smb);

  // ---- prefetch K/V tile 0 into raw stage ----
  #pragma unroll
  for (int i = 0; i < 8; ++i) {
    uint32_t off = (uint32_t)(i * 256 + tid) * 16u;
    CPA16(smu + RAWK_B + off, (const char*)Kb + off);
    CPA16(smu + RAWV_B + off, (const char*)Vb + off);
  }
  CPA_COMMIT();

  // ---- load + split Q tile into bf16 hi/lo planes ----
  __nv_bfloat16* smbh = (__nv_bfloat16*)smb;
  #pragma unroll
  for (int i = 0; i < 16; ++i) {
    int idx = i * THREADS + tid;
    int row = idx >> 5;
    int c4  = (idx & 31) * 4;
    float4 v = *reinterpret_cast<const float4*>(Qb + row * D_HEAD + c4);
    uint32_t h01, l01, h23, l23;
    split2(v.x, v.y, h01, l01);
    split2(v.z, v.w, h23, l23);
    *reinterpret_cast<uint2*>(smbh + QH_E + row * STR + c4) = make_uint2(h01, h23);
    *reinterpret_cast<uint2*>(smbh + QL_E + row * STR + c4) = make_uint2(l01, l23);
  }

  // ldsm per-lane base addresses (byte units)
  const uint32_t qbase = smu + 2u * ((row0 + (lane & 15)) * STR + (lane >> 4) * 8);
  const uint32_t kbase = smu + 2u * (((lane & 7) + ((lane >> 4) << 3)) * STR
                                     + (((lane >> 3) & 1) << 3));
  const uint32_t vbase = smu + 2u * (((lane & 7) + (((lane >> 3) & 1) << 3)) * STR
                                     + ((lane >> 4) << 3));

  float o[16][4];
  #pragma unroll
  for (int n = 0; n < 16; ++n) { o[n][0] = o[n][1] = o[n][2] = o[n][3] = 0.f; }
  float mA = -INFINITY, mB = -INFINITY;
  float lA = 0.f, lB = 0.f;

  const float* rawk = (const float*)(smb + RAWK_B);
  const float* rawv = (const float*)(smb + RAWV_B);

  for (int t = 0; t < NT; ++t) {
    // ---- raw(t) landed; planes(t-1) fully consumed ----
    CPA_WAIT0();
    __syncthreads();

    // ---- convert raw -> K bf16 hi/lo planes, V fp16 plane ----
    #pragma unroll
    for (int i = 0; i < 8; ++i) {
      int idx = i * THREADS + tid;
      int row = idx >> 5;
      int c4  = (idx & 31) * 4;
      float4 kv = *reinterpret_cast<const float4*>(rawk + idx * 4);
      uint32_t h01, l01, h23, l23;
      split2(kv.x, kv.y, h01, l01);
      split2(kv.z, kv.w, h23, l23);
      *reinterpret_cast<uint2*>(smbh + KH_E + row * STR + c4) = make_uint2(h01, h23);
      *reinterpret_cast<uint2*>(smbh + KL_E + row * STR + c4) = make_uint2(l01, l23);
      float4 vv = *reinterpret_cast<const float4*>(rawv + idx * 4);
      __half2 v01 = __floats2half2_rn(vv.x, vv.y);
      __half2 v23 = __floats2half2_rn(vv.z, vv.w);
      *reinterpret_cast<uint2*>(smbh + VF_E + row * STR + c4) =
          make_uint2(*reinterpret_cast<uint32_t*>(&v01),
                     *reinterpret_cast<uint32_t*>(&v23));
    }
    __syncthreads();

    // ---- prefetch tile t+1 into (now free) raw stage ----
    if (t + 1 < NT) {
      const char* Kt = (const char*)(Kb + (size_t)(t + 1) * BN * D_HEAD);
      const char* Vt = (const char*)(Vb + (size_t)(t + 1) * BN * D_HEAD);
      #pragma unroll
      for (int i = 0; i < 8; ++i) {
        uint32_t off = (uint32_t)(i * 256 + tid) * 16u;
        CPA16(smu + RAWK_B + off, Kt + off);
        CPA16(smu + RAWV_B + off, Vt + off);
      }
      CPA_COMMIT();
    }

    // ---- S = Q K^T : 3-term split-bf16 ----
    float s[8][4];
    #pragma unroll
    for (int n = 0; n < 8; ++n) { s[n][0] = s[n][1] = s[n][2] = s[n][3] = 0.f; }

    #pragma unroll
    for (int c = 0; c < 8; ++c) {
      const int kc = c * 16;
      uint32_t qh[4], ql[4];
      ldsm4(qh, qbase + 2u * (QH_E + kc));
      ldsm4(ql, qbase + 2u * (QL_E + kc));
      #pragma unroll
      for (int n2 = 0; n2 < 4; ++n2) {
        uint32_t kh[4], kl[4];
        ldsm4(kh, kbase + 2u * (KH_E + n2 * 16 * STR + kc));
        ldsm4(kl, kbase + 2u * (KL_E + n2 * 16 * STR + kc));
        mma16b(s[2 * n2],     qh, kh[0], kh[1]);
        mma16b(s[2 * n2 + 1], qh, kh[2], kh[3]);
        mma16b(s[2 * n2],     qh, kl[0], kl[1]);
        mma16b(s[2 * n2 + 1], qh, kl[2], kl[3]);
        mma16b(s[2 * n2],     ql, kh[0], kh[1]);
        mma16b(s[2 * n2 + 1], ql, kh[2], kh[3]);
      }
    }

    // ---- online softmax ----
    float mx0 = s[0][0], mx1 = s[0][2];
    #pragma unroll
    for (int n = 0; n < 8; ++n) {
      mx0 = fmaxf(mx0, fmaxf(s[n][0], s[n][1]));
      mx1 = fmaxf(mx1, fmaxf(s[n][2], s[n][3]));
    }
    mx0 = fmaxf(mx0, __shfl_xor_sync(0xffffffffu, mx0, 1));
    mx0 = fmaxf(mx0, __shfl_xor_sync(0xffffffffu, mx0, 2));
    mx1 = fmaxf(mx1, __shfl_xor_sync(0xffffffffu, mx1, 1));
    mx1 = fmaxf(mx1, __shfl_xor_sync(0xffffffffu, mx1, 2));

    float mnA = fmaxf(mA, mx0);
    float mnB = fmaxf(mB, mx1);
    float aAc = ex2f((mA - mnA) * LOG2E);
    float aBc = ex2f((mB - mnB) * LOG2E);

    // P -> fp16 pairs; normalizer from the QUANTIZED values
    uint32_t p2[16];
    float psA = 0.f, psB = 0.f;
    #pragma unroll
    for (int n = 0; n < 8; ++n) {
      __half2 hA = __floats2half2_rn(ex2f((s[n][0] - mnA) * LOG2E),
                                     ex2f((s[n][1] - mnA) * LOG2E));
      __half2 hB = __floats2half2_rn(ex2f((s[n][2] - mnB) * LOG2E),
                                     ex2f((s[n][3] - mnB) * LOG2E));
      p2[2 * n]     = *reinterpret_cast<uint32_t*>(&hA);
      p2[2 * n + 1] = *reinterpret_cast<uint32_t*>(&hB);
      float2 fA = __half22float2(hA);
      float2 fB = __half22float2(hB);
      psA += fA.x + fA.y;
      psB += fB.x + fB.y;
    }
    psA += __shfl_xor_sync(0xffffffffu, psA, 1);
    psA += __shfl_xor_sync(0xffffffffu, psA, 2);
    psB += __shfl_xor_sync(0xffffffffu, psB, 1);
    psB += __shfl_xor_sync(0xffffffffu, psB, 2);

    lA = lA * aAc + psA;
    lB = lB * aBc + psB;
    mA = mnA; mB = mnB;

    #pragma unroll
    for (int n = 0; n < 16; ++n) {
      o[n][0] *= aAc; o[n][1] *= aAc;
      o[n][2] *= aBc; o[n][3] *= aBc;
    }

    // ---- O += P V : single-term fp16 ----
    #pragma unroll
    for (int c = 0; c < 4; ++c) {
      const int kc = c * 16;
      const uint32_t aP[4] = { p2[4 * c], p2[4 * c + 1], p2[4 * c + 2], p2[4 * c + 3] };
      #pragma unroll
      for (int n2 = 0; n2 < 8; ++n2) {
        uint32_t vh[4];
        ldsm4t(vh, vbase + 2u * (VF_E + kc * STR + n2 * 16));
        mma16h(o[2 * n2],     aP, vh[0], vh[1]);
        mma16h(o[2 * n2 + 1], aP, vh[2], vh[3]);
      }
    }
  }

  // ---- epilogue: O / l ----
  const int gid = lane >> 2;
  const int tg  = lane & 3;
  const float ilA = 1.f / lA;
  const float ilB = 1.f / lB;
  float* Ob = Og + base + (size_t)q0 * D_HEAD;
  #pragma unroll
  for (int n = 0; n < 16; ++n) {
    int col = n * 8 + 2 * tg;
    *reinterpret_cast<float2*>(Ob + (size_t)(row0 + gid) * D_HEAD + col) =
        make_float2(o[n][0] * ilA, o[n][1] * ilA);
    *reinterpret_cast<float2*>(Ob + (size_t)(row0 + gid + 8) * D_HEAD + col) =
        make_float2(o[n][2] * ilB, o[n][3] * ilB);
  }
}

extern "C" void kernel_launch(void* const* d_in, const int* in_sizes, int n_in,
                              void* d_out, int out_size) {
  const float* Q = (const float*)d_in[0];
  const float* K = (const float*)d_in[1];
  const float* V = (const float*)d_in[2];
  float* O = (float*)d_out;

  cudaFuncSetAttribute(fattn_h, cudaFuncAttributeMaxDynamicSharedMemorySize,
                       SMEM_BYTES);
  dim3 grid(S_LEN / BM, N_BH);
  fattn_h<<<grid, THREADS, SMEM_BYTES>>>(Q, K, V, O);
}